// round 4
// baseline (speedup 1.0000x reference)
#include <cuda_runtime.h>
#include <math.h>

#define BB 256
#define NN 384
#define DD 128
#define NEGV -1e9f
#define NTHR 384

// ---------------------------------------------------------------------------
// Bit-faithful port of XLA's EmitFastTanh with with_fma=true:
//   clamp to +-7.99881172180175781 (the FMA-path clamp constant),
//   13/6 rational with Eigen alpha/beta coefficients, FMA Horner,
//   |x| < 0.0004 -> x.
// ---------------------------------------------------------------------------
__device__ __forceinline__ float xla_tanh(float x) {
    const float kClamp = 7.99881172180175781f;   // with_fma clamp
    float xc = fminf(fmaxf(x, -kClamp), kClamp);
    float x2 = xc * xc;
    float p = fmaf(x2, -2.76076847742355e-16f, 2.00018790482477e-13f);
    p = fmaf(x2, p, -8.60467152213735e-11f);
    p = fmaf(x2, p,  5.12229709037114e-08f);
    p = fmaf(x2, p,  1.48572235717979e-05f);
    p = fmaf(x2, p,  6.37261928875436e-04f);
    p = fmaf(x2, p,  4.89352455891786e-03f);
    p = xc * p;
    float q = fmaf(x2, 1.19825839466702e-06f, 1.18534705686654e-04f);
    q = fmaf(x2, q, 2.26843463243900e-03f);
    q = fmaf(x2, q, 4.89352518554385e-03f);
    float r = p / q;
    return (fabsf(x) < 0.0004f) ? x : r;
}

extern __shared__ float smem[];

// One CTA per batch. Thread n owns node n: KV[n][0..127] in registers.
__global__ void __launch_bounds__(NTHR, 1)
decode_kernel(const float* __restrict__ hvec,
              const float* __restrict__ hbar,
              const float* __restrict__ qvp,
              const float* __restrict__ kvp,
              const float* __restrict__ vec1,
              const float* __restrict__ vecf,
              float* __restrict__ out)
{
    const int b    = blockIdx.x;
    const int tid  = threadIdx.x;
    const int lane = tid & 31;
    const int wid  = tid >> 5;

    float* W    = smem;              // [DD*DD]: kv_p in prologue, qv_p in loop
    float* ctx  = W + DD * DD;       // [DD]
    float* hb   = ctx + DD;          // [DD]
    float* fst  = hb + DD;           // [DD] 'first' vector (set at t=0)
    float* qs   = fst + DD;          // [DD] per-step q
    float* rv   = qs + DD;           // [16] argmax partial values
    int*   ri   = (int*)(rv + 16);   // [16] argmax partial indices
    float* rs   = (float*)(ri + 16); // [16] expsum partials
    float* resv = rs + 16;           // [1] block max
    int*   resi = (int*)(resv + 1);  // [1] block argmax

    // ---- Prologue 1: stage kv_p into SMEM ----
    for (int i = tid; i < DD * DD; i += NTHR) W[i] = kvp[i];
    __syncthreads();

    // ---- Prologue 2: KV[ij] = sum_k kv_p[k,ij] * h[k], sequential k ----
    float KV[DD];
    #pragma unroll
    for (int j = 0; j < DD; j++) KV[j] = 0.f;

    const float* hrow = hvec + ((size_t)b * NN + tid) * DD;
    for (int kc = 0; kc < DD; kc += 16) {
        float4 h4[4];
        #pragma unroll
        for (int i = 0; i < 4; i++)
            h4[i] = ((const float4*)hrow)[kc / 4 + i];
        const float* hs = (const float*)h4;
        #pragma unroll
        for (int i = 0; i < 16; i++) {
            float hk = hs[i];
            const float4* row = (const float4*)(W + (kc + i) * DD);
            #pragma unroll
            for (int j4 = 0; j4 < 32; j4++) {
                float4 w = row[j4];
                KV[4 * j4 + 0] = fmaf(w.x, hk, KV[4 * j4 + 0]);
                KV[4 * j4 + 1] = fmaf(w.y, hk, KV[4 * j4 + 1]);
                KV[4 * j4 + 2] = fmaf(w.z, hk, KV[4 * j4 + 2]);
                KV[4 * j4 + 3] = fmaf(w.w, hk, KV[4 * j4 + 3]);
            }
        }
    }
    __syncthreads();

    // ---- Prologue 3: stage qv_p (overwrites kv_p); init ctx ----
    for (int i = tid; i < DD * DD; i += NTHR) W[i] = qvp[i];
    if (tid < DD) {
        float hbv = hbar[b * DD + tid];
        hb[tid]  = hbv;
        ctx[tid] = (hbv + vec1[tid]) + vecf[tid];
    }
    __syncthreads();

    bool visited = false;
    float logp = 0.f;

    for (int t = 0; t < NN; t++) {
        // 1. q[ij] = sum_k ctx[k] * qv_p[k,ij]  (threads 0..127, sequential k)
        if (tid < DD) {
            float acc = 0.f;
            #pragma unroll 16
            for (int k = 0; k < DD; k++)
                acc = fmaf(ctx[k], W[k * DD + tid], acc);
            qs[tid] = acc;
        }
        __syncthreads();  // (A)

        // 2. score: single sequential accumulator over ij
        float s = 0.f;
        const float4* q4 = (const float4*)qs;
        #pragma unroll
        for (int j4 = 0; j4 < 32; j4++) {
            float4 q = q4[j4];
            s = fmaf(q.x, KV[4 * j4 + 0], s);
            s = fmaf(q.y, KV[4 * j4 + 1], s);
            s = fmaf(q.z, KV[4 * j4 + 2], s);
            s = fmaf(q.w, KV[4 * j4 + 3], s);
        }
        float score  = 10.f * xla_tanh(s * 0.25f);
        float masked = visited ? NEGV : score;

        // 3. warp argmax (lowest index wins ties, matching jnp.argmax)
        float v = masked;
        int   idx = tid;
        #pragma unroll
        for (int o = 16; o > 0; o >>= 1) {
            float v2 = __shfl_xor_sync(0xffffffffu, v, o);
            int   i2 = __shfl_xor_sync(0xffffffffu, idx, o);
            if (v2 > v || (v2 == v && i2 < idx)) { v = v2; idx = i2; }
        }
        if (lane == 0) { rv[wid] = v; ri[wid] = idx; }
        __syncthreads();  // (B)

        // 4. cross-warp argmax by warp 0
        if (tid < 32) {
            float v1 = (lane < 12) ? rv[lane] : -3.0e38f;
            int   i1 = (lane < 12) ? ri[lane] : 0x7fffffff;
            #pragma unroll
            for (int o = 8; o > 0; o >>= 1) {
                float v2 = __shfl_xor_sync(0xffffffffu, v1, o);
                int   i2 = __shfl_xor_sync(0xffffffffu, i1, o);
                if (v2 > v1 || (v2 == v1 && i2 < i1)) { v1 = v2; i1 = i2; }
            }
            if (lane == 0) { resv[0] = v1; resi[0] = i1; }
        }
        __syncthreads();  // (C)

        const float mx = resv[0];
        const int   a  = resi[0];

        // 5. exp-sum partials; state updates; next ctx
        float e = expf(masked - mx);  // visited -> 0
        #pragma unroll
        for (int o = 16; o > 0; o >>= 1)
            e += __shfl_xor_sync(0xffffffffu, e, o);
        if (lane == 0) rs[wid] = e;

        if (tid == a)  visited = true;
        if (tid == 0)  out[t * BB + b] = (float)a;  // pi[t][b]

        if (tid >= 256) {
            int k = tid - 256;
            float ha = __ldg(hvec + ((size_t)b * NN + a) * DD + k);  // L2-hot
            if (t == 0) fst[k] = ha;            // first := chosen at t=0
            ctx[k] = (hb[k] + ha) + fst[k];     // (hbar + last) + first
        }
        __syncthreads();  // (D)

        // 6. finalize logp (warp 0); rs stable until after next (C)
        if (tid < 32) {
            float sum = (lane < 12) ? rs[lane] : 0.f;
            #pragma unroll
            for (int o = 8; o > 0; o >>= 1)
                sum += __shfl_xor_sync(0xffffffffu, sum, o);
            if (lane == 0) logp -= logf(sum);   // logpol[a] = -log(sumexp)
        }
    }

    if (tid == 0) out[NN * BB + b] = logp;
}

// ---------------------------------------------------------------------------
extern "C" void kernel_launch(void* const* d_in, const int* in_sizes, int n_in,
                              void* d_out, int out_size) {
    const float* hvec = (const float*)d_in[0];  // [B,N,D]
    const float* hbar = (const float*)d_in[1];  // [B,D]
    const float* qvp  = (const float*)d_in[2];  // [D,128]
    const float* kvp  = (const float*)d_in[3];  // [D,128]
    const float* vec1 = (const float*)d_in[4];  // [D]
    const float* vecf = (const float*)d_in[5];  // [D]
    float* out = (float*)d_out;                 // [N*B] pi + [B] logp

    size_t smem_bytes = (size_t)(DD * DD + 4 * DD + 16 + 16 + 16 + 4) * sizeof(float);
    cudaFuncSetAttribute(decode_kernel,
                         cudaFuncAttributeMaxDynamicSharedMemorySize,
                         (int)smem_bytes);
    decode_kernel<<<BB, NTHR, smem_bytes>>>(hvec, hbar, qvp, kvp, vec1, vecf, out);
}

// round 5
// speedup vs baseline: 1.5815x; 1.5815x over previous
#include <cuda_runtime.h>
#include <math.h>

#define BB 256
#define NN 384
#define DD 128
#define NEGV -1e9f
#define NTHR 384
#define USTRIDE 136   // 16B-aligned row stride for U table

// SMEM float offsets
#define OFF_U     0
#define OFF_QHB   (NN * USTRIDE)          // 52224
#define OFF_QV1F  (OFF_QHB + DD)          // 52352
#define OFF_RV    (OFF_QV1F + DD)         // 52480
#define OFF_RI    (OFF_RV + 16)
#define OFF_RS    (OFF_RI + 16)
#define OFF_RESI  (OFF_RS + 16)
#define OFF_SCR   52544                    // 16B aligned scratch, 4096 floats
#define SMEM_FLOATS (OFF_SCR + 32 * DD)    // 56640 floats = 226560 B

// ---------------------------------------------------------------------------
// Bit-faithful port of XLA's EmitFastTanh (with_fma=true). DO NOT TOUCH:
// the route's tie structure depends on this exact function.
// ---------------------------------------------------------------------------
__device__ __forceinline__ float xla_tanh(float x) {
    const float kClamp = 7.99881172180175781f;
    float xc = fminf(fmaxf(x, -kClamp), kClamp);
    float x2 = xc * xc;
    float p = fmaf(x2, -2.76076847742355e-16f, 2.00018790482477e-13f);
    p = fmaf(x2, p, -8.60467152213735e-11f);
    p = fmaf(x2, p,  5.12229709037114e-08f);
    p = fmaf(x2, p,  1.48572235717979e-05f);
    p = fmaf(x2, p,  6.37261928875436e-04f);
    p = fmaf(x2, p,  4.89352455891786e-03f);
    p = xc * p;
    float q = fmaf(x2, 1.19825839466702e-06f, 1.18534705686654e-04f);
    q = fmaf(x2, q, 2.26843463243900e-03f);
    q = fmaf(x2, q, 4.89352518554385e-03f);
    float r = p / q;
    return (fabsf(x) < 0.0004f) ? x : r;
}

extern __shared__ float smem[];

__global__ void __launch_bounds__(NTHR, 1)
decode_kernel(const float* __restrict__ hvec,
              const float* __restrict__ hbar,
              const float* __restrict__ qvp,
              const float* __restrict__ kvp,
              const float* __restrict__ vec1,
              const float* __restrict__ vecf,
              float* __restrict__ out)
{
    const int b    = blockIdx.x;
    const int tid  = threadIdx.x;
    const int lane = tid & 31;
    const int wid  = tid >> 5;

    float* Us   = smem + OFF_U;
    float* qhb  = smem + OFF_QHB;
    float* qv1f = smem + OFF_QV1F;
    float* rv   = smem + OFF_RV;
    int*   ri   = (int*)(smem + OFF_RI);
    float* rs   = smem + OFF_RS;
    int*   resi = (int*)(smem + OFF_RESI);
    float* scr  = smem + OFF_SCR;

    const float* hrow = hvec + ((size_t)b * NN + tid) * DD;

    // ================= PROLOGUE =================
    // Phase A: stage qvp flat into U area; hbar row & (vec1+vecf) into scratch
    for (int i = tid; i < DD * DD; i += NTHR) Us[i] = qvp[i];
    if (tid < DD) {
        scr[tid]      = hbar[b * DD + tid];
        scr[DD + tid] = vec1[tid] + vecf[tid];
    }
    __syncthreads();

    // Phase B: U[n][ij] = sum_k qvp[k][ij] * h[n][k], sequential-k per output
    float Ur[DD];
    #pragma unroll
    for (int j = 0; j < DD; j++) Ur[j] = 0.f;
    for (int kc = 0; kc < DD; kc += 16) {
        float4 h4[4];
        #pragma unroll
        for (int i = 0; i < 4; i++) h4[i] = ((const float4*)hrow)[kc / 4 + i];
        const float* hs = (const float*)h4;
        #pragma unroll
        for (int i = 0; i < 16; i++) {
            float hk = hs[i];
            const float4* row = (const float4*)(Us + (kc + i) * DD);
            #pragma unroll
            for (int j4 = 0; j4 < 32; j4++) {
                float4 w = row[j4];
                Ur[4 * j4 + 0] = fmaf(w.x, hk, Ur[4 * j4 + 0]);
                Ur[4 * j4 + 1] = fmaf(w.y, hk, Ur[4 * j4 + 1]);
                Ur[4 * j4 + 2] = fmaf(w.z, hk, Ur[4 * j4 + 2]);
                Ur[4 * j4 + 3] = fmaf(w.w, hk, Ur[4 * j4 + 3]);
            }
        }
    }
    // Phase B2: qhb = Wq^T hbar ; qv1f = Wq^T (vec1+vecf)   (threads 0..127)
    if (tid < DD) {
        float a0 = 0.f, a1 = 0.f, a2 = 0.f, a3 = 0.f;
        float c0 = 0.f, c1 = 0.f, c2 = 0.f, c3 = 0.f;
        #pragma unroll 8
        for (int k = 0; k < DD; k += 4) {
            float w0 = Us[(k + 0) * DD + tid];
            float w1 = Us[(k + 1) * DD + tid];
            float w2 = Us[(k + 2) * DD + tid];
            float w3 = Us[(k + 3) * DD + tid];
            a0 = fmaf(w0, scr[k + 0], a0); c0 = fmaf(w0, scr[DD + k + 0], c0);
            a1 = fmaf(w1, scr[k + 1], a1); c1 = fmaf(w1, scr[DD + k + 1], c1);
            a2 = fmaf(w2, scr[k + 2], a2); c2 = fmaf(w2, scr[DD + k + 2], c2);
            a3 = fmaf(w3, scr[k + 3], a3); c3 = fmaf(w3, scr[DD + k + 3], c3);
        }
        qhb[tid]  = (a0 + a1) + (a2 + a3);
        qv1f[tid] = (c0 + c1) + (c2 + c3);
    }
    __syncthreads();

    // Phase C: write U registers -> strided SMEM rows (overwrites qvp staging)
    {
        float4* myrow = (float4*)(Us + tid * USTRIDE);
        #pragma unroll
        for (int j4 = 0; j4 < 32; j4++)
            myrow[j4] = make_float4(Ur[4 * j4], Ur[4 * j4 + 1],
                                    Ur[4 * j4 + 2], Ur[4 * j4 + 3]);
    }

    // Phase D: KV[ij] = sum_k kvp[k][ij]*h[k], sequential-k, 4 staged chunks
    float KV[DD];
    #pragma unroll
    for (int j = 0; j < DD; j++) KV[j] = 0.f;
    for (int c = 0; c < 4; c++) {
        __syncthreads();  // previous scratch readers done
        for (int i = tid; i < 32 * DD; i += NTHR) scr[i] = kvp[c * 32 * DD + i];
        __syncthreads();
        for (int kc = 0; kc < 32; kc += 16) {
            float4 h4[4];
            #pragma unroll
            for (int i = 0; i < 4; i++)
                h4[i] = ((const float4*)hrow)[(c * 32 + kc) / 4 + i];
            const float* hs = (const float*)h4;
            #pragma unroll
            for (int i = 0; i < 16; i++) {
                float hk = hs[i];
                const float4* row = (const float4*)(scr + (kc + i) * DD);
                #pragma unroll
                for (int j4 = 0; j4 < 32; j4++) {
                    float4 w = row[j4];
                    KV[4 * j4 + 0] = fmaf(w.x, hk, KV[4 * j4 + 0]);
                    KV[4 * j4 + 1] = fmaf(w.y, hk, KV[4 * j4 + 1]);
                    KV[4 * j4 + 2] = fmaf(w.z, hk, KV[4 * j4 + 2]);
                    KV[4 * j4 + 3] = fmaf(w.w, hk, KV[4 * j4 + 3]);
                }
            }
        }
    }
    __syncthreads();

    // Phase E: sHB = qhb.KV ; sV = qv1f.KV
    float sHB, sV;
    {
        float a0 = 0.f, a1 = 0.f, a2 = 0.f, a3 = 0.f;
        float c0 = 0.f, c1 = 0.f, c2 = 0.f, c3 = 0.f;
        const float4* q4 = (const float4*)qhb;
        const float4* v4 = (const float4*)qv1f;
        #pragma unroll
        for (int j4 = 0; j4 < 32; j4++) {
            float4 q = q4[j4], v = v4[j4];
            a0 = fmaf(q.x, KV[4 * j4 + 0], a0); c0 = fmaf(v.x, KV[4 * j4 + 0], c0);
            a1 = fmaf(q.y, KV[4 * j4 + 1], a1); c1 = fmaf(v.y, KV[4 * j4 + 1], c1);
            a2 = fmaf(q.z, KV[4 * j4 + 2], a2); c2 = fmaf(v.z, KV[4 * j4 + 2], c2);
            a3 = fmaf(q.w, KV[4 * j4 + 3], a3); c3 = fmaf(v.w, KV[4 * j4 + 3], c3);
        }
        sHB = (a0 + a1) + (a2 + a3);
        sV  = (c0 + c1) + (c2 + c3);
    }

    // ================= MAIN DECODE LOOP (2 barriers/step) =================
    bool  vis  = false;
    float logp = 0.f;
    float sbf  = 0.f;
    int   a    = -1;

    for (int t = 0; t < NN; t++) {
        float s;
        if (t == 0) {
            s = sHB + sV;
        } else {
            const float4* ur = (const float4*)(Us + a * USTRIDE);
            float d0 = 0.f, d1 = 0.f, d2 = 0.f, d3 = 0.f;
            #pragma unroll
            for (int j4 = 0; j4 < 32; j4++) {
                float4 u = ur[j4];
                d0 = fmaf(u.x, KV[4 * j4 + 0], d0);
                d1 = fmaf(u.y, KV[4 * j4 + 1], d1);
                d2 = fmaf(u.z, KV[4 * j4 + 2], d2);
                d3 = fmaf(u.w, KV[4 * j4 + 3], d3);
            }
            float dt = (d0 + d1) + (d2 + d3);
            if (t == 1) sbf = sHB + dt;   // first := chosen at t=0
            s = sbf + dt;
        }

        float score  = 10.f * xla_tanh(s * 0.25f);
        float masked = vis ? NEGV : score;
        float ep     = __expf(masked);     // exp(-1e9) -> 0

        // fused warp argmax (lowest index on ties) + exp-sum
        float v = masked; int idx = tid; float es = ep;
        #pragma unroll
        for (int o = 16; o > 0; o >>= 1) {
            float v2 = __shfl_xor_sync(0xffffffffu, v, o);
            int   i2 = __shfl_xor_sync(0xffffffffu, idx, o);
            float e2 = __shfl_xor_sync(0xffffffffu, es, o);
            es += e2;
            if (v2 > v || (v2 == v && i2 < idx)) { v = v2; idx = i2; }
        }
        if (lane == 0) { rv[wid] = v; ri[wid] = idx; rs[wid] = es; }
        __syncthreads();  // (1)

        if (tid < 32) {
            float v1 = (lane < 12) ? rv[lane] : -3.0e38f;
            int   i1 = (lane < 12) ? ri[lane] : 0x7fffffff;
            float ss = (lane < 12) ? rs[lane] : 0.f;
            #pragma unroll
            for (int o = 8; o > 0; o >>= 1) {
                float v2 = __shfl_xor_sync(0xffffffffu, v1, o);
                int   i2 = __shfl_xor_sync(0xffffffffu, i1, o);
                float s2 = __shfl_xor_sync(0xffffffffu, ss, o);
                ss += s2;
                if (v2 > v1 || (v2 == v1 && i2 < i1)) { v1 = v2; i1 = i2; }
            }
            if (lane == 0) {
                resi[0] = i1;
                out[t * BB + b] = (float)i1;
                logp += v1 - __logf(ss);  // = -log(sum exp(masked - max))
            }
        }
        __syncthreads();  // (2)

        a = resi[0];
        if (tid == a) vis = true;
    }

    if (tid == 0) out[NN * BB + b] = logp;
}

// ---------------------------------------------------------------------------
extern "C" void kernel_launch(void* const* d_in, const int* in_sizes, int n_in,
                              void* d_out, int out_size) {
    const float* hvec = (const float*)d_in[0];
    const float* hbar = (const float*)d_in[1];
    const float* qvp  = (const float*)d_in[2];
    const float* kvp  = (const float*)d_in[3];
    const float* vec1 = (const float*)d_in[4];
    const float* vecf = (const float*)d_in[5];
    float* out = (float*)d_out;

    size_t smem_bytes = (size_t)SMEM_FLOATS * sizeof(float);  // 226560 B
    cudaFuncSetAttribute(decode_kernel,
                         cudaFuncAttributeMaxDynamicSharedMemorySize,
                         (int)smem_bytes);
    decode_kernel<<<BB, NTHR, smem_bytes>>>(hvec, hbar, qvp, kvp, vec1, vecf, out);
}